// round 12
// baseline (speedup 1.0000x reference)
#include <cuda_runtime.h>
#include <cstdint>

#define DD 4096
#define LL 6
#define BLOCK 1024
#define NST 3                     // staging slots (4 rows each)
#define STAGE_BYTES (4 * DD * 4)  // 65536 B per quad

// ---- mbarrier / bulk-copy helpers ----
__device__ __forceinline__ uint32_t smem_u32(const void* p) {
    return (uint32_t)__cvta_generic_to_shared(p);
}
__device__ __forceinline__ void mbar_init(uint64_t* m, uint32_t cnt) {
    asm volatile("mbarrier.init.shared.b64 [%0], %1;" :: "r"(smem_u32(m)), "r"(cnt) : "memory");
}
__device__ __forceinline__ void mbar_expect_tx(uint64_t* m, uint32_t bytes) {
    asm volatile("mbarrier.arrive.expect_tx.shared.b64 _, [%0], %1;"
                 :: "r"(smem_u32(m)), "r"(bytes) : "memory");
}
__device__ __forceinline__ void mbar_wait(uint64_t* m, uint32_t phase) {
    uint32_t a = smem_u32(m);
    asm volatile(
        "{\n\t.reg .pred P;\n\t"
        "WAIT_%=:\n\t"
        "mbarrier.try_wait.parity.acquire.cta.shared::cta.b64 P, [%0], %1, 0x989680;\n\t"
        "@P bra DONE_%=;\n\t"
        "bra WAIT_%=;\n\t"
        "DONE_%=:\n\t}"
        :: "r"(a), "r"(phase) : "memory");
}
__device__ __forceinline__ void bulk_ld(float* dst, const float* src, uint32_t bytes, uint64_t* m) {
    asm volatile(
        "cp.async.bulk.shared::cluster.global.mbarrier::complete_tx::bytes [%0], [%1], %2, [%3];"
        :: "r"(smem_u32(dst)), "l"(src), "r"(bytes), "r"(smem_u32(m)) : "memory");
}

// 8-value transposed warp reduce: 9 SHFL; on return p[0] holds value
// idx = lane>>2, fully reduced, replicated over lanes {4i..4i+3}.
__device__ __forceinline__ void reduce8(float* p, int lane) {
    {
        bool hi = (lane & 16) != 0;
#pragma unroll
        for (int j = 0; j < 4; j++) {
            float send = hi ? p[j] : p[j + 4];
            float keep = hi ? p[j + 4] : p[j];
            p[j] = keep + __shfl_xor_sync(0xffffffffu, send, 16);
        }
    }
    {
        bool hi = (lane & 8) != 0;
#pragma unroll
        for (int j = 0; j < 2; j++) {
            float send = hi ? p[j] : p[j + 2];
            float keep = hi ? p[j + 2] : p[j];
            p[j] = keep + __shfl_xor_sync(0xffffffffu, send, 8);
        }
    }
    {
        bool hi = (lane & 4) != 0;
        float send = hi ? p[0] : p[1];
        float keep = hi ? p[1] : p[0];
        p[0] = keep + __shfl_xor_sync(0xffffffffu, send, 4);
    }
    p[0] += __shfl_xor_sync(0xffffffffu, p[0], 2);
    p[0] += __shfl_xor_sync(0xffffffffu, p[0], 1);
}

__global__ __launch_bounds__(BLOCK, 1)
void crossnet_dcn_kernel(const float* __restrict__ x0g,
                         const float* __restrict__ wg,
                         const float* __restrict__ bg,
                         float* __restrict__ outg,
                         int B)
{
    extern __shared__ float xs[];        // NST * 4 * DD floats (x0 staging, TMA-filled)
    __shared__ float s_part[32][25];     // 24 reduced values per warp, pad 25
    __shared__ float s_c[2][4];          // double-buffered c scalars (4 rows)
    __shared__ float s_e[LL];            // e_l scalars
    __shared__ __align__(8) uint64_t mbar[NST];

    const int tid  = threadIdx.x;
    const int lane = tid & 31;
    const int wid  = tid >> 5;

    const float4* w4 = reinterpret_cast<const float4*>(wg);
    const float4* b4 = reinterpret_cast<const float4*>(bg);
    float4*       o4 = reinterpret_cast<float4*>(outg);

    // ---- w for this thread's 4 columns, all layers (24 regs) ----
    float4 wr[LL];
#pragma unroll
    for (int l = 0; l < LL; l++) wr[l] = w4[l * (DD / 4) + tid];

    // ---- mbarrier init (count=1: single expect_tx arrival per phase) ----
    if (tid == 0) {
#pragma unroll
        for (int s = 0; s < NST; s++) mbar_init(&mbar[s], 1);
    }

    // ---- preamble: d_L (vector, regs) and e_l = d_l . w_l -> s_e ----
    float4 dl = make_float4(0.f, 0.f, 0.f, 0.f);
    {
        float ep[LL];
#pragma unroll
        for (int l = 0; l < LL; l++) {
            ep[l] = dl.x * wr[l].x + dl.y * wr[l].y + dl.z * wr[l].z + dl.w * wr[l].w;
            float4 bv = b4[l * (DD / 4) + tid];
            dl.x += bv.x; dl.y += bv.y; dl.z += bv.z; dl.w += bv.w;
        }
#pragma unroll
        for (int o = 16; o > 0; o >>= 1)
#pragma unroll
            for (int l = 0; l < LL; l++) ep[l] += __shfl_xor_sync(0xffffffffu, ep[l], o);
        if (lane == 0)
#pragma unroll
            for (int l = 0; l < LL; l++) s_part[wid][l] = ep[l];
    }
    __syncthreads();     // also makes mbar init visible
    if (wid == 0) {
#pragma unroll
        for (int l = 0; l < LL; l++) {
            float t = s_part[lane][l];
#pragma unroll
            for (int o = 16; o > 0; o >>= 1) t += __shfl_xor_sync(0xffffffffu, t, o);
            if (lane == 0) s_e[l] = t;
        }
    }
    __syncthreads();

    // ---- main loop: 4 rows ("quad") per iteration, ONE block barrier/iter ----
    const int nquads = B >> 2;
    const int stride = gridDim.x;
    const int bid    = blockIdx.x;
    const int niters = (nquads > bid) ? (nquads - bid + stride - 1) / stride : 0;

    // prologue: issue stages 0 and 1
    if (tid == 0) {
#pragma unroll
        for (int ia = 0; ia < 2; ia++) {
            int qn = bid + ia * stride;
            if (qn < nquads) {
                mbar_expect_tx(&mbar[ia], STAGE_BYTES);
                bulk_ld(xs + ia * 4 * DD, x0g + (size_t)(4 * qn) * DD, STAGE_BYTES, &mbar[ia]);
            }
        }
    }

    // running 32-bit float4 indices (max ~16.7M < 2^31)
    const uint32_t ostep = (uint32_t)stride * 4u * (DD / 4);
    uint32_t oidx = (uint32_t)bid * 4u * (DD / 4) + tid;   // quad it=0 row 0

    for (int it = 0; it < niters; it++) {
        const int slot = it % NST;
        const uint32_t parity = (uint32_t)((it / NST) & 1);
        mbar_wait(&mbar[slot], parity);          // acquire: TMA data visible

        const float* xb = xs + slot * 4 * DD + tid * 4;
        const int  cur = it & 1;

        // ---- stage-1: 24 partial dots (4 rows x 6 layers), rows transient ----
        float v[24];
#pragma unroll
        for (int r = 0; r < 4; r++) {
            const float4 x = *reinterpret_cast<const float4*>(xb + r * DD);
#pragma unroll
            for (int l = 0; l < LL; l++) {
                float a = x.x * wr[l].x;
                a = fmaf(x.y, wr[l].y, a);
                a = fmaf(x.z, wr[l].z, a);
                a = fmaf(x.w, wr[l].w, a);
                v[6 * r + l] = a;
            }
        }

        // ---- three pad-free 8-value reduces (27 SHFL total) ----
#pragma unroll
        for (int g = 0; g < 3; g++) {
            reduce8(&v[8 * g], lane);
            if ((lane & 3) == 0)
                s_part[wid][8 * g + (lane >> 2)] = v[8 * g];
        }

        __syncthreads();   // the ONLY block barrier per iteration

        // ---- all warps: epilogue for quad i-1 FIRST (issue DRAM writes early) ----
        if (it > 0) {
            const float* pb = xs + ((it - 1) % NST) * 4 * DD + tid * 4;
            const uint32_t op = oidx - ostep;
            const float  c0 = s_c[cur ^ 1][0], c1 = s_c[cur ^ 1][1];
            const float  c2 = s_c[cur ^ 1][2], c3 = s_c[cur ^ 1][3];
            float4 xp, o;
            xp = *reinterpret_cast<const float4*>(pb + 0 * DD);
            o.x = fmaf(xp.x, c0, dl.x); o.y = fmaf(xp.y, c0, dl.y);
            o.z = fmaf(xp.z, c0, dl.z); o.w = fmaf(xp.w, c0, dl.w);
            __stcs(&o4[op], o);
            xp = *reinterpret_cast<const float4*>(pb + 1 * DD);
            o.x = fmaf(xp.x, c1, dl.x); o.y = fmaf(xp.y, c1, dl.y);
            o.z = fmaf(xp.z, c1, dl.z); o.w = fmaf(xp.w, c1, dl.w);
            __stcs(&o4[op + (DD / 4)], o);
            xp = *reinterpret_cast<const float4*>(pb + 2 * DD);
            o.x = fmaf(xp.x, c2, dl.x); o.y = fmaf(xp.y, c2, dl.y);
            o.z = fmaf(xp.z, c2, dl.z); o.w = fmaf(xp.w, c2, dl.w);
            __stcs(&o4[op + 2 * (DD / 4)], o);
            xp = *reinterpret_cast<const float4*>(pb + 3 * DD);
            o.x = fmaf(xp.x, c3, dl.x); o.y = fmaf(xp.y, c3, dl.y);
            o.z = fmaf(xp.z, c3, dl.z); o.w = fmaf(xp.w, c3, dl.w);
            __stcs(&o4[op + 3 * (DD / 4)], o);
        }

        // ---- warps 0-3: stage-2 for quad i (consumed next iteration) ----
        if (wid < 4) {
            float t[6];
#pragma unroll
            for (int l = 0; l < LL; l++) t[l] = s_part[lane][6 * wid + l];
            // 6-value reduce over 32 lanes (pad to 8): 9 SHFL
            {
                bool hi = (lane & 16) != 0;
#pragma unroll
                for (int j = 0; j < 4; j++) {
                    float th   = (j + 4 < 6) ? t[j + 4] : 0.f;
                    float send = hi ? t[j] : th;
                    float keep = hi ? th : t[j];
                    t[j] = keep + __shfl_xor_sync(0xffffffffu, send, 16);
                }
            }
            {
                bool hi = (lane & 8) != 0;
#pragma unroll
                for (int j = 0; j < 2; j++) {
                    float send = hi ? t[j] : t[j + 2];
                    float keep = hi ? t[j + 2] : t[j];
                    t[j] = keep + __shfl_xor_sync(0xffffffffu, send, 8);
                }
            }
            {
                bool hi = (lane & 4) != 0;
                float send = hi ? t[0] : t[1];
                float keep = hi ? t[1] : t[0];
                t[0] = keep + __shfl_xor_sync(0xffffffffu, send, 4);
            }
            t[0] += __shfl_xor_sync(0xffffffffu, t[0], 2);
            t[0] += __shfl_xor_sync(0xffffffffu, t[0], 1);

            float c = 1.f;
#pragma unroll
            for (int l = 0; l < LL; l++) {
                float u = __shfl_sync(0xffffffffu, t[0], 4 * l);
                c = fmaf(c, u, c + s_e[l]);   // c = c*(1+u) + e
            }
            if (lane == 0) s_c[cur][wid] = c;
        }

        // ---- producer-gated refill of slot (it+2)%3 == (it-1)%3 ----
        if (wid != 31) {
            asm volatile("bar.arrive 1, %0;" :: "r"(BLOCK) : "memory");
        } else {
            asm volatile("bar.sync 1, %0;" :: "r"(BLOCK) : "memory");
            const int ia = it + 2;
            const int qn = bid + ia * stride;
            if (qn < nquads && lane == 0) {
                const int s = ia % NST;
                mbar_expect_tx(&mbar[s], STAGE_BYTES);
                bulk_ld(xs + s * 4 * DD, x0g + (size_t)(4 * qn) * DD, STAGE_BYTES, &mbar[s]);
            }
        }

        oidx += ostep;
    }

    // ---- drain: epilogue for the last quad ----
    if (niters > 0) {
        __syncthreads();   // make warps 0-3's s_c write visible
        const int it  = niters - 1;
        const int cur = it & 1;
        const float* pb = xs + (it % NST) * 4 * DD + tid * 4;
        const uint32_t op = oidx - ostep;   // last quad's base
        const float  c0 = s_c[cur][0], c1 = s_c[cur][1];
        const float  c2 = s_c[cur][2], c3 = s_c[cur][3];
        float4 xp, o;
        xp = *reinterpret_cast<const float4*>(pb + 0 * DD);
        o.x = fmaf(xp.x, c0, dl.x); o.y = fmaf(xp.y, c0, dl.y);
        o.z = fmaf(xp.z, c0, dl.z); o.w = fmaf(xp.w, c0, dl.w);
        __stcs(&o4[op], o);
        xp = *reinterpret_cast<const float4*>(pb + 1 * DD);
        o.x = fmaf(xp.x, c1, dl.x); o.y = fmaf(xp.y, c1, dl.y);
        o.z = fmaf(xp.z, c1, dl.z); o.w = fmaf(xp.w, c1, dl.w);
        __stcs(&o4[op + (DD / 4)], o);
        xp = *reinterpret_cast<const float4*>(pb + 2 * DD);
        o.x = fmaf(xp.x, c2, dl.x); o.y = fmaf(xp.y, c2, dl.y);
        o.z = fmaf(xp.z, c2, dl.z); o.w = fmaf(xp.w, c2, dl.w);
        __stcs(&o4[op + 2 * (DD / 4)], o);
        xp = *reinterpret_cast<const float4*>(pb + 3 * DD);
        o.x = fmaf(xp.x, c3, dl.x); o.y = fmaf(xp.y, c3, dl.y);
        o.z = fmaf(xp.z, c3, dl.z); o.w = fmaf(xp.w, c3, dl.w);
        __stcs(&o4[op + 3 * (DD / 4)], o);
    }
}

extern "C" void kernel_launch(void* const* d_in, const int* in_sizes, int n_in,
                              void* d_out, int out_size)
{
    const float* x0 = (const float*)d_in[0];   // inputs [B, D] f32
    const float* w  = (const float*)d_in[1];   // w [L, D, 1]  f32
    const float* b  = (const float*)d_in[2];   // b [L, D]     f32
    float* out      = (float*)d_out;           // [B, D]       f32

    const int B = in_sizes[0] / DD;
    const int smem_bytes = NST * 4 * DD * (int)sizeof(float);   // 196608

    static int sm_count = 0;
    if (sm_count == 0) {
        cudaDeviceGetAttribute(&sm_count, cudaDevAttrMultiProcessorCount, 0);
        if (sm_count <= 0) sm_count = 148;
        cudaFuncSetAttribute(crossnet_dcn_kernel,
                             cudaFuncAttributeMaxDynamicSharedMemorySize,
                             smem_bytes);
    }

    crossnet_dcn_kernel<<<sm_count, BLOCK, smem_bytes>>>(x0, w, b, out, B);
}

// round 13
// speedup vs baseline: 1.0066x; 1.0066x over previous
#include <cuda_runtime.h>
#include <cstdint>

#define DD 4096
#define LL 6
#define BLOCK 1024
#define NST 3                     // staging slots (4 rows each)
#define STAGE_BYTES (4 * DD * 4)  // 65536 B per quad

// ---- mbarrier / bulk-copy helpers ----
__device__ __forceinline__ uint32_t smem_u32(const void* p) {
    return (uint32_t)__cvta_generic_to_shared(p);
}
__device__ __forceinline__ void mbar_init(uint64_t* m, uint32_t cnt) {
    asm volatile("mbarrier.init.shared.b64 [%0], %1;" :: "r"(smem_u32(m)), "r"(cnt) : "memory");
}
__device__ __forceinline__ void mbar_expect_tx(uint64_t* m, uint32_t bytes) {
    asm volatile("mbarrier.arrive.expect_tx.shared.b64 _, [%0], %1;"
                 :: "r"(smem_u32(m)), "r"(bytes) : "memory");
}
__device__ __forceinline__ void mbar_wait(uint64_t* m, uint32_t phase) {
    uint32_t a = smem_u32(m);
    asm volatile(
        "{\n\t.reg .pred P;\n\t"
        "WAIT_%=:\n\t"
        "mbarrier.try_wait.parity.acquire.cta.shared::cta.b64 P, [%0], %1, 0x989680;\n\t"
        "@P bra DONE_%=;\n\t"
        "bra WAIT_%=;\n\t"
        "DONE_%=:\n\t}"
        :: "r"(a), "r"(phase) : "memory");
}
__device__ __forceinline__ void bulk_ld(float* dst, const float* src, uint32_t bytes, uint64_t* m) {
    asm volatile(
        "cp.async.bulk.shared::cluster.global.mbarrier::complete_tx::bytes [%0], [%1], %2, [%3];"
        :: "r"(smem_u32(dst)), "l"(src), "r"(bytes), "r"(smem_u32(m)) : "memory");
}

__global__ __launch_bounds__(BLOCK, 1)
void crossnet_dcn_kernel(const float* __restrict__ x0g,
                         const float* __restrict__ wg,
                         const float* __restrict__ bg,
                         float* __restrict__ outg,
                         int B)
{
    extern __shared__ float xs[];        // NST * 4 * DD floats (x0 staging, TMA-filled)
    __shared__ float s_part[32][25];     // 24 reduced values per warp, pad 25
    __shared__ float s_c[2][4];          // double-buffered c scalars (4 rows)
    __shared__ float s_e[LL];            // e_l scalars
    __shared__ __align__(8) uint64_t mbar[NST];

    const int tid  = threadIdx.x;
    const int lane = tid & 31;
    const int wid  = tid >> 5;

    const float4* w4 = reinterpret_cast<const float4*>(wg);
    const float4* b4 = reinterpret_cast<const float4*>(bg);
    float4*       o4 = reinterpret_cast<float4*>(outg);

    // ---- w for this thread's 4 columns, all layers (24 regs) ----
    float4 wr[LL];
#pragma unroll
    for (int l = 0; l < LL; l++) wr[l] = w4[l * (DD / 4) + tid];

    // ---- mbarrier init (count=1: single expect_tx arrival per phase) ----
    if (tid == 0) {
#pragma unroll
        for (int s = 0; s < NST; s++) mbar_init(&mbar[s], 1);
    }

    // ---- preamble: d_L (vector, regs) and e_l = d_l . w_l -> s_e ----
    float4 dl = make_float4(0.f, 0.f, 0.f, 0.f);
    {
        float ep[LL];
#pragma unroll
        for (int l = 0; l < LL; l++) {
            ep[l] = dl.x * wr[l].x + dl.y * wr[l].y + dl.z * wr[l].z + dl.w * wr[l].w;
            float4 bv = b4[l * (DD / 4) + tid];
            dl.x += bv.x; dl.y += bv.y; dl.z += bv.z; dl.w += bv.w;
        }
#pragma unroll
        for (int o = 16; o > 0; o >>= 1)
#pragma unroll
            for (int l = 0; l < LL; l++) ep[l] += __shfl_xor_sync(0xffffffffu, ep[l], o);
        if (lane == 0)
#pragma unroll
            for (int l = 0; l < LL; l++) s_part[wid][l] = ep[l];
    }
    __syncthreads();     // also makes mbar init visible
    if (wid == 0) {
#pragma unroll
        for (int l = 0; l < LL; l++) {
            float t = s_part[lane][l];
#pragma unroll
            for (int o = 16; o > 0; o >>= 1) t += __shfl_xor_sync(0xffffffffu, t, o);
            if (lane == 0) s_e[l] = t;
        }
    }
    __syncthreads();

    // ---- main loop: 4 rows ("quad") per iteration, ONE block barrier/iter ----
    const int nquads = B >> 2;
    const int stride = gridDim.x;
    const int bid    = blockIdx.x;
    const int niters = (nquads > bid) ? (nquads - bid + stride - 1) / stride : 0;

    // prologue: issue stages 0 and 1
    if (tid == 0) {
#pragma unroll
        for (int ia = 0; ia < 2; ia++) {
            int qn = bid + ia * stride;
            if (qn < nquads) {
                mbar_expect_tx(&mbar[ia], STAGE_BYTES);
                bulk_ld(xs + ia * 4 * DD, x0g + (size_t)(4 * qn) * DD, STAGE_BYTES, &mbar[ia]);
            }
        }
    }

    // running 32-bit float4 output index (max ~16.7M < 2^31)
    const uint32_t ostep = (uint32_t)stride * 4u * (DD / 4);
    uint32_t oidx = (uint32_t)bid * 4u * (DD / 4) + (uint32_t)tid;

    for (int it = 0; it < niters; it++) {
        const int slot = it % NST;
        const uint32_t parity = (uint32_t)((it / NST) & 1);
        mbar_wait(&mbar[slot], parity);          // acquire: TMA data visible

        const float* xb = xs + slot * 4 * DD + tid * 4;
        const int  cur = it & 1;

        float v[12];

        // ---- half 0: rows 0,1 ----
        {
            const float4 xr0 = *reinterpret_cast<const float4*>(xb + 0 * DD);
            const float4 xr1 = *reinterpret_cast<const float4*>(xb + 1 * DD);
#pragma unroll
            for (int l = 0; l < LL; l++) {
                float a = xr0.x * wr[l].x;
                a = fmaf(xr0.y, wr[l].y, a);
                a = fmaf(xr0.z, wr[l].z, a);
                a = fmaf(xr0.w, wr[l].w, a);
                v[l] = a;
                float c = xr1.x * wr[l].x;
                c = fmaf(xr1.y, wr[l].y, c);
                c = fmaf(xr1.z, wr[l].z, c);
                c = fmaf(xr1.w, wr[l].w, c);
                v[LL + l] = c;
            }
        }
        {
            bool hi = (lane & 16) != 0;
#pragma unroll
            for (int j = 0; j < 8; j++) {
                float vh   = (j + 8 < 12) ? v[j + 8] : 0.f;
                float send = hi ? v[j] : vh;
                float keep = hi ? vh : v[j];
                v[j] = keep + __shfl_xor_sync(0xffffffffu, send, 16);
            }
        }
#pragma unroll
        for (int r = 1; r < 4; r++) {
            const int dist = 16 >> r;
            const int nv   = 8 >> r;
            bool hi = (lane & dist) != 0;
#pragma unroll
            for (int j = 0; j < nv; j++) {
                float send = hi ? v[j] : v[j + nv];
                float keep = hi ? v[j + nv] : v[j];
                v[j] = keep + __shfl_xor_sync(0xffffffffu, send, dist);
            }
        }
        v[0] += __shfl_xor_sync(0xffffffffu, v[0], 1);
        if ((lane & 1) == 0 && lane < 24)
            s_part[wid][lane >> 1] = v[0];

        // ---- half 1: rows 2,3 ----
        {
            const float4 xr2 = *reinterpret_cast<const float4*>(xb + 2 * DD);
            const float4 xr3 = *reinterpret_cast<const float4*>(xb + 3 * DD);
#pragma unroll
            for (int l = 0; l < LL; l++) {
                float a = xr2.x * wr[l].x;
                a = fmaf(xr2.y, wr[l].y, a);
                a = fmaf(xr2.z, wr[l].z, a);
                a = fmaf(xr2.w, wr[l].w, a);
                v[l] = a;
                float c = xr3.x * wr[l].x;
                c = fmaf(xr3.y, wr[l].y, c);
                c = fmaf(xr3.z, wr[l].z, c);
                c = fmaf(xr3.w, wr[l].w, c);
                v[LL + l] = c;
            }
        }
        {
            bool hi = (lane & 16) != 0;
#pragma unroll
            for (int j = 0; j < 8; j++) {
                float vh   = (j + 8 < 12) ? v[j + 8] : 0.f;
                float send = hi ? v[j] : vh;
                float keep = hi ? vh : v[j];
                v[j] = keep + __shfl_xor_sync(0xffffffffu, send, 16);
            }
        }
#pragma unroll
        for (int r = 1; r < 4; r++) {
            const int dist = 16 >> r;
            const int nv   = 8 >> r;
            bool hi = (lane & dist) != 0;
#pragma unroll
            for (int j = 0; j < nv; j++) {
                float send = hi ? v[j] : v[j + nv];
                float keep = hi ? v[j + nv] : v[j];
                v[j] = keep + __shfl_xor_sync(0xffffffffu, send, dist);
            }
        }
        v[0] += __shfl_xor_sync(0xffffffffu, v[0], 1);
        if ((lane & 1) == 0 && lane < 24)
            s_part[wid][12 + (lane >> 1)] = v[0];

        __syncthreads();   // the ONLY block barrier per iteration

        // ---- all warps: epilogue for quad i-1 FIRST (DRAM writes in flight early) ----
        if (it > 0) {
            const float* pb = xs + ((it - 1) % NST) * 4 * DD + tid * 4;
            const uint32_t op = oidx - ostep;
            const float  c0 = s_c[cur ^ 1][0], c1 = s_c[cur ^ 1][1];
            const float  c2 = s_c[cur ^ 1][2], c3 = s_c[cur ^ 1][3];
            float4 xp, o;
            xp = *reinterpret_cast<const float4*>(pb + 0 * DD);
            o.x = fmaf(xp.x, c0, dl.x); o.y = fmaf(xp.y, c0, dl.y);
            o.z = fmaf(xp.z, c0, dl.z); o.w = fmaf(xp.w, c0, dl.w);
            __stcs(&o4[op], o);
            xp = *reinterpret_cast<const float4*>(pb + 1 * DD);
            o.x = fmaf(xp.x, c1, dl.x); o.y = fmaf(xp.y, c1, dl.y);
            o.z = fmaf(xp.z, c1, dl.z); o.w = fmaf(xp.w, c1, dl.w);
            __stcs(&o4[op + (DD / 4)], o);
            xp = *reinterpret_cast<const float4*>(pb + 2 * DD);
            o.x = fmaf(xp.x, c2, dl.x); o.y = fmaf(xp.y, c2, dl.y);
            o.z = fmaf(xp.z, c2, dl.z); o.w = fmaf(xp.w, c2, dl.w);
            __stcs(&o4[op + 2 * (DD / 4)], o);
            xp = *reinterpret_cast<const float4*>(pb + 3 * DD);
            o.x = fmaf(xp.x, c3, dl.x); o.y = fmaf(xp.y, c3, dl.y);
            o.z = fmaf(xp.z, c3, dl.z); o.w = fmaf(xp.w, c3, dl.w);
            __stcs(&o4[op + 3 * (DD / 4)], o);
        }

        // ---- warps 0-3: stage-2 for quad i (consumed next iteration) ----
        if (wid < 4) {
            float t[6];
#pragma unroll
            for (int l = 0; l < LL; l++) t[l] = s_part[lane][6 * wid + l];
            {
                bool hi = (lane & 16) != 0;
#pragma unroll
                for (int j = 0; j < 4; j++) {
                    float th   = (j + 4 < 6) ? t[j + 4] : 0.f;
                    float send = hi ? t[j] : th;
                    float keep = hi ? th : t[j];
                    t[j] = keep + __shfl_xor_sync(0xffffffffu, send, 16);
                }
            }
            {
                bool hi = (lane & 8) != 0;
#pragma unroll
                for (int j = 0; j < 2; j++) {
                    float send = hi ? t[j] : t[j + 2];
                    float keep = hi ? t[j + 2] : t[j];
                    t[j] = keep + __shfl_xor_sync(0xffffffffu, send, 8);
                }
            }
            {
                bool hi = (lane & 4) != 0;
                float send = hi ? t[0] : t[1];
                float keep = hi ? t[1] : t[0];
                t[0] = keep + __shfl_xor_sync(0xffffffffu, send, 4);
            }
            t[0] += __shfl_xor_sync(0xffffffffu, t[0], 2);
            t[0] += __shfl_xor_sync(0xffffffffu, t[0], 1);

            float c = 1.f;
#pragma unroll
            for (int l = 0; l < LL; l++) {
                float u = __shfl_sync(0xffffffffu, t[0], 4 * l);
                c = fmaf(c, u, c + s_e[l]);   // c = c*(1+u) + e
            }
            if (lane == 0) s_c[cur][wid] = c;
        }

        // ---- producer-gated refill of slot (it+2)%3 == (it-1)%3 ----
        if (wid != 31) {
            asm volatile("bar.arrive 1, %0;" :: "r"(BLOCK) : "memory");
        } else {
            asm volatile("bar.sync 1, %0;" :: "r"(BLOCK) : "memory");
            const int ia = it + 2;
            const int qn = bid + ia * stride;
            if (qn < nquads && lane == 0) {
                const int s = ia % NST;
                mbar_expect_tx(&mbar[s], STAGE_BYTES);
                bulk_ld(xs + s * 4 * DD, x0g + (size_t)(4 * qn) * DD, STAGE_BYTES, &mbar[s]);
            }
        }

        oidx += ostep;
    }

    // ---- drain: epilogue for the last quad ----
    if (niters > 0) {
        __syncthreads();   // make warps 0-3's s_c write visible
        const int it  = niters - 1;
        const int cur = it & 1;
        const float* pb = xs + (it % NST) * 4 * DD + tid * 4;
        const uint32_t op = oidx - ostep;   // last quad's base
        const float  c0 = s_c[cur][0], c1 = s_c[cur][1];
        const float  c2 = s_c[cur][2], c3 = s_c[cur][3];
        float4 xp, o;
        xp = *reinterpret_cast<const float4*>(pb + 0 * DD);
        o.x = fmaf(xp.x, c0, dl.x); o.y = fmaf(xp.y, c0, dl.y);
        o.z = fmaf(xp.z, c0, dl.z); o.w = fmaf(xp.w, c0, dl.w);
        __stcs(&o4[op], o);
        xp = *reinterpret_cast<const float4*>(pb + 1 * DD);
        o.x = fmaf(xp.x, c1, dl.x); o.y = fmaf(xp.y, c1, dl.y);
        o.z = fmaf(xp.z, c1, dl.z); o.w = fmaf(xp.w, c1, dl.w);
        __stcs(&o4[op + (DD / 4)], o);
        xp = *reinterpret_cast<const float4*>(pb + 2 * DD);
        o.x = fmaf(xp.x, c2, dl.x); o.y = fmaf(xp.y, c2, dl.y);
        o.z = fmaf(xp.z, c2, dl.z); o.w = fmaf(xp.w, c2, dl.w);
        __stcs(&o4[op + 2 * (DD / 4)], o);
        xp = *reinterpret_cast<const float4*>(pb + 3 * DD);
        o.x = fmaf(xp.x, c3, dl.x); o.y = fmaf(xp.y, c3, dl.y);
        o.z = fmaf(xp.z, c3, dl.z); o.w = fmaf(xp.w, c3, dl.w);
        __stcs(&o4[op + 3 * (DD / 4)], o);
    }
}

extern "C" void kernel_launch(void* const* d_in, const int* in_sizes, int n_in,
                              void* d_out, int out_size)
{
    const float* x0 = (const float*)d_in[0];   // inputs [B, D] f32
    const float* w  = (const float*)d_in[1];   // w [L, D, 1]  f32
    const float* b  = (const float*)d_in[2];   // b [L, D]     f32
    float* out      = (float*)d_out;           // [B, D]       f32

    const int B = in_sizes[0] / DD;
    const int smem_bytes = NST * 4 * DD * (int)sizeof(float);   // 196608

    static int sm_count = 0;
    if (sm_count == 0) {
        cudaDeviceGetAttribute(&sm_count, cudaDevAttrMultiProcessorCount, 0);
        if (sm_count <= 0) sm_count = 148;
        cudaFuncSetAttribute(crossnet_dcn_kernel,
                             cudaFuncAttributeMaxDynamicSharedMemorySize,
                             smem_bytes);
    }

    crossnet_dcn_kernel<<<sm_count, BLOCK, smem_bytes>>>(x0, w, b, out, B);
}

// round 15
// speedup vs baseline: 1.0173x; 1.0106x over previous
#include <cuda_runtime.h>
#include <cstdint>

#define DD 4096
#define LL 6
#define BLOCK 1024
#define NST 3                     // staging slots (4 rows each)
#define STAGE_BYTES (4 * DD * 4)  // 65536 B per quad

// ---- mbarrier / bulk-copy helpers ----
__device__ __forceinline__ uint32_t smem_u32(const void* p) {
    return (uint32_t)__cvta_generic_to_shared(p);
}
__device__ __forceinline__ void mbar_init(uint64_t* m, uint32_t cnt) {
    asm volatile("mbarrier.init.shared.b64 [%0], %1;" :: "r"(smem_u32(m)), "r"(cnt) : "memory");
}
__device__ __forceinline__ void mbar_expect_tx(uint64_t* m, uint32_t bytes) {
    asm volatile("mbarrier.arrive.expect_tx.shared.b64 _, [%0], %1;"
                 :: "r"(smem_u32(m)), "r"(bytes) : "memory");
}
__device__ __forceinline__ void mbar_wait(uint64_t* m, uint32_t phase) {
    uint32_t a = smem_u32(m);
    asm volatile(
        "{\n\t.reg .pred P;\n\t"
        "WAIT_%=:\n\t"
        "mbarrier.try_wait.parity.acquire.cta.shared::cta.b64 P, [%0], %1, 0x989680;\n\t"
        "@P bra DONE_%=;\n\t"
        "bra WAIT_%=;\n\t"
        "DONE_%=:\n\t}"
        :: "r"(a), "r"(phase) : "memory");
}
__device__ __forceinline__ void bulk_ld(float* dst, const float* src, uint32_t bytes, uint64_t* m) {
    asm volatile(
        "cp.async.bulk.shared::cluster.global.mbarrier::complete_tx::bytes [%0], [%1], %2, [%3];"
        :: "r"(smem_u32(dst)), "l"(src), "r"(bytes), "r"(smem_u32(m)) : "memory");
}

// 8-value transposed warp reduce: 9 SHFL; on return p[0] holds value
// idx = lane>>2, fully reduced, replicated over lanes {4i..4i+3}.
__device__ __forceinline__ void reduce8(float* p, int lane) {
    {
        bool hi = (lane & 16) != 0;
#pragma unroll
        for (int j = 0; j < 4; j++) {
            float send = hi ? p[j] : p[j + 4];
            float keep = hi ? p[j + 4] : p[j];
            p[j] = keep + __shfl_xor_sync(0xffffffffu, send, 16);
        }
    }
    {
        bool hi = (lane & 8) != 0;
#pragma unroll
        for (int j = 0; j < 2; j++) {
            float send = hi ? p[j] : p[j + 2];
            float keep = hi ? p[j + 2] : p[j];
            p[j] = keep + __shfl_xor_sync(0xffffffffu, send, 8);
        }
    }
    {
        bool hi = (lane & 4) != 0;
        float send = hi ? p[0] : p[1];
        float keep = hi ? p[1] : p[0];
        p[0] = keep + __shfl_xor_sync(0xffffffffu, send, 4);
    }
    p[0] += __shfl_xor_sync(0xffffffffu, p[0], 2);
    p[0] += __shfl_xor_sync(0xffffffffu, p[0], 1);
}

__device__ __forceinline__ float dot4(const float4 x, const float4 w) {
    float a = x.x * w.x;
    a = fmaf(x.y, w.y, a);
    a = fmaf(x.z, w.z, a);
    a = fmaf(x.w, w.w, a);
    return a;
}

__global__ __launch_bounds__(BLOCK, 1)
void crossnet_dcn_kernel(const float* __restrict__ x0g,
                         const float* __restrict__ wg,
                         const float* __restrict__ bg,
                         float* __restrict__ outg,
                         int B)
{
    extern __shared__ float xs[];        // NST * 4 * DD floats (TMA staging)
    __shared__ float s_part[32][25];     // 24 values/warp (idx = 6r+l), stride 25
    __shared__ float s_c[2][4];          // double-buffered c scalars (4 rows)
    __shared__ float s_e[LL];            // e_l scalars
    __shared__ __align__(8) uint64_t mbar[NST];

    const int tid  = threadIdx.x;
    const int lane = tid & 31;
    const int wid  = tid >> 5;

    const float4* w4 = reinterpret_cast<const float4*>(wg);
    const float4* b4 = reinterpret_cast<const float4*>(bg);
    float4*       o4 = reinterpret_cast<float4*>(outg);

    // ---- w for this thread's 4 columns, all layers (24 regs) ----
    float4 wr[LL];
#pragma unroll
    for (int l = 0; l < LL; l++) wr[l] = w4[l * (DD / 4) + tid];

    // ---- mbarrier init (count=1: single expect_tx arrival per phase) ----
    if (tid == 0) {
#pragma unroll
        for (int s = 0; s < NST; s++) mbar_init(&mbar[s], 1);
    }

    // ---- preamble: d_L (vector, regs) and e_l = d_l . w_l -> s_e ----
    float4 dl = make_float4(0.f, 0.f, 0.f, 0.f);
    {
        float ep[LL];
#pragma unroll
        for (int l = 0; l < LL; l++) {
            ep[l] = dl.x * wr[l].x + dl.y * wr[l].y + dl.z * wr[l].z + dl.w * wr[l].w;
            float4 bv = b4[l * (DD / 4) + tid];
            dl.x += bv.x; dl.y += bv.y; dl.z += bv.z; dl.w += bv.w;
        }
#pragma unroll
        for (int o = 16; o > 0; o >>= 1)
#pragma unroll
            for (int l = 0; l < LL; l++) ep[l] += __shfl_xor_sync(0xffffffffu, ep[l], o);
        if (lane == 0)
#pragma unroll
            for (int l = 0; l < LL; l++) s_part[wid][l] = ep[l];
    }
    __syncthreads();     // also makes mbar init visible
    if (wid == 0) {
#pragma unroll
        for (int l = 0; l < LL; l++) {
            float t = s_part[lane][l];
#pragma unroll
            for (int o = 16; o > 0; o >>= 1) t += __shfl_xor_sync(0xffffffffu, t, o);
            if (lane == 0) s_e[l] = t;
        }
    }
    __syncthreads();

    // ---- main loop: 4 rows ("quad") per iteration, ONE block barrier/iter ----
    const int nquads = B >> 2;
    const int stride = gridDim.x;
    const int bid    = blockIdx.x;
    const int niters = (nquads > bid) ? (nquads - bid + stride - 1) / stride : 0;

    // prologue: issue stages 0 and 1
    if (tid == 0) {
#pragma unroll
        for (int ia = 0; ia < 2; ia++) {
            int qn = bid + ia * stride;
            if (qn < nquads) {
                mbar_expect_tx(&mbar[ia], STAGE_BYTES);
                bulk_ld(xs + ia * 4 * DD, x0g + (size_t)(4 * qn) * DD, STAGE_BYTES, &mbar[ia]);
            }
        }
    }

    // running 32-bit float4 output index (max ~16.7M < 2^31)
    const uint32_t ostep = (uint32_t)stride * 4u * (DD / 4);
    uint32_t oidx = (uint32_t)bid * 4u * (DD / 4) + (uint32_t)tid;

    for (int it = 0; it < niters; it++) {
        const int slot = it % NST;
        const uint32_t parity = (uint32_t)((it / NST) & 1);
        mbar_wait(&mbar[slot], parity);          // acquire: TMA data visible

        const float* xb = xs + slot * 4 * DD + tid * 4;
        const int  cur = it & 1;

        // ---- stage-1: 24 dots in three pad-free 8-value groups,
        //      reduces interleaved with dot computation.
        //      flat value idx = 6r+l = 8g+j; stored at s_part[wid][idx]. ----
        {
            const float4 xr0 = *reinterpret_cast<const float4*>(xb + 0 * DD);
            const float4 xr1 = *reinterpret_cast<const float4*>(xb + 1 * DD);
            float v[12];
#pragma unroll
            for (int l = 0; l < LL; l++) v[l]      = dot4(xr0, wr[l]);
#pragma unroll
            for (int l = 0; l < LL; l++) v[LL + l] = dot4(xr1, wr[l]);

            // group 0: idx 0..7 (r0 l0-5, r1 l0-1)
            reduce8(v, lane);
            if ((lane & 3) == 0) s_part[wid][lane >> 2] = v[0];

            // group 1: idx 8..15 (r1 l2-5, r2 l0-3)
            const float4 xr2 = *reinterpret_cast<const float4*>(xb + 2 * DD);
            float g[8];
            g[0] = v[8]; g[1] = v[9]; g[2] = v[10]; g[3] = v[11];
#pragma unroll
            for (int l = 0; l < 4; l++) g[4 + l] = dot4(xr2, wr[l]);
            reduce8(g, lane);
            if ((lane & 3) == 0) s_part[wid][8 + (lane >> 2)] = g[0];

            // group 2: idx 16..23 (r2 l4-5, r3 l0-5)
            const float4 xr3 = *reinterpret_cast<const float4*>(xb + 3 * DD);
            float h[8];
            h[0] = dot4(xr2, wr[4]);
            h[1] = dot4(xr2, wr[5]);
#pragma unroll
            for (int l = 0; l < LL; l++) h[2 + l] = dot4(xr3, wr[l]);
            reduce8(h, lane);
            if ((lane & 3) == 0) s_part[wid][16 + (lane >> 2)] = h[0];
        }

        __syncthreads();   // the ONLY block barrier per iteration

        // ---- all warps: epilogue for quad i-1 FIRST (DRAM writes in flight early) ----
        if (it > 0) {
            const float* pb = xs + ((it - 1) % NST) * 4 * DD + tid * 4;
            const uint32_t op = oidx - ostep;
            const float  c0 = s_c[cur ^ 1][0], c1 = s_c[cur ^ 1][1];
            const float  c2 = s_c[cur ^ 1][2], c3 = s_c[cur ^ 1][3];
            float4 xp, o;
            xp = *reinterpret_cast<const float4*>(pb + 0 * DD);
            o.x = fmaf(xp.x, c0, dl.x); o.y = fmaf(xp.y, c0, dl.y);
            o.z = fmaf(xp.z, c0, dl.z); o.w = fmaf(xp.w, c0, dl.w);
            __stcs(&o4[op], o);
            xp = *reinterpret_cast<const float4*>(pb + 1 * DD);
            o.x = fmaf(xp.x, c1, dl.x); o.y = fmaf(xp.y, c1, dl.y);
            o.z = fmaf(xp.z, c1, dl.z); o.w = fmaf(xp.w, c1, dl.w);
            __stcs(&o4[op + (DD / 4)], o);
            xp = *reinterpret_cast<const float4*>(pb + 2 * DD);
            o.x = fmaf(xp.x, c2, dl.x); o.y = fmaf(xp.y, c2, dl.y);
            o.z = fmaf(xp.z, c2, dl.z); o.w = fmaf(xp.w, c2, dl.w);
            __stcs(&o4[op + 2 * (DD / 4)], o);
            xp = *reinterpret_cast<const float4*>(pb + 3 * DD);
            o.x = fmaf(xp.x, c3, dl.x); o.y = fmaf(xp.y, c3, dl.y);
            o.z = fmaf(xp.z, c3, dl.z); o.w = fmaf(xp.w, c3, dl.w);
            __stcs(&o4[op + 3 * (DD / 4)], o);
        }

        // ---- warps 0-3: stage-2 for quad i (consumed next iteration) ----
        if (wid < 4) {
            float t[6];
#pragma unroll
            for (int l = 0; l < LL; l++) t[l] = s_part[lane][6 * wid + l];
            {
                bool hi = (lane & 16) != 0;
#pragma unroll
                for (int j = 0; j < 4; j++) {
                    float th   = (j + 4 < 6) ? t[j + 4] : 0.f;
                    float send = hi ? t[j] : th;
                    float keep = hi ? th : t[j];
                    t[j] = keep + __shfl_xor_sync(0xffffffffu, send, 16);
                }
            }
            {
                bool hi = (lane & 8) != 0;
#pragma unroll
                for (int j = 0; j < 2; j++) {
                    float send = hi ? t[j] : t[j + 2];
                    float keep = hi ? t[j + 2] : t[j];
                    t[j] = keep + __shfl_xor_sync(0xffffffffu, send, 8);
                }
            }
            {
                bool hi = (lane & 4) != 0;
                float send = hi ? t[0] : t[1];
                float keep = hi ? t[1] : t[0];
                t[0] = keep + __shfl_xor_sync(0xffffffffu, send, 4);
            }
            t[0] += __shfl_xor_sync(0xffffffffu, t[0], 2);
            t[0] += __shfl_xor_sync(0xffffffffu, t[0], 1);

            float c = 1.f;
#pragma unroll
            for (int l = 0; l < LL; l++) {
                float u = __shfl_sync(0xffffffffu, t[0], 4 * l);
                c = fmaf(c, u, c + s_e[l]);   // c = c*(1+u) + e
            }
            if (lane == 0) s_c[cur][wid] = c;
        }

        // ---- producer-gated refill of slot (it+2)%3 == (it-1)%3 ----
        if (wid != 31) {
            asm volatile("bar.arrive 1, %0;" :: "r"(BLOCK) : "memory");
        } else {
            asm volatile("bar.sync 1, %0;" :: "r"(BLOCK) : "memory");
            const int ia = it + 2;
            const int qn = bid + ia * stride;
            if (qn < nquads && lane == 0) {
                const int s = ia % NST;
                mbar_expect_tx(&mbar[s], STAGE_BYTES);
                bulk_ld(xs + s * 4 * DD, x0g + (size_t)(4 * qn) * DD, STAGE_BYTES, &mbar[s]);
            }
        }

        oidx += ostep;
    }

    // ---- drain: epilogue for the last quad ----
    if (niters > 0) {
        __syncthreads();   // make warps 0-3's s_c write visible
        const int it  = niters - 1;
        const int cur = it & 1;
        const float* pb = xs + (it % NST) * 4 * DD + tid * 4;
        const uint32_t op = oidx - ostep;   // last quad's base
        const float  c0 = s_c[cur][0], c1 = s_c[cur][1];
        const float  c2 = s_c[cur][2], c3 = s_c[cur][3];
        float4 xp, o;
        xp = *reinterpret_cast<const float4*>(pb + 0 * DD);
        o.x = fmaf(xp.x, c0, dl.x); o.y = fmaf(xp.y, c0, dl.y);
        o.z = fmaf(xp.z, c0, dl.z); o.w = fmaf(xp.w, c0, dl.w);
        __stcs(&o4[op], o);
        xp = *reinterpret_cast<const float4*>(pb + 1 * DD);
        o.x = fmaf(xp.x, c1, dl.x); o.y = fmaf(xp.y, c1, dl.y);
        o.z = fmaf(xp.z, c1, dl.z); o.w = fmaf(xp.w, c1, dl.w);
        __stcs(&o4[op + (DD / 4)], o);
        xp = *reinterpret_cast<const float4*>(pb + 2 * DD);
        o.x = fmaf(xp.x, c2, dl.x); o.y = fmaf(xp.y, c2, dl.y);
        o.z = fmaf(xp.z, c2, dl.z); o.w = fmaf(xp.w, c2, dl.w);
        __stcs(&o4[op + 2 * (DD / 4)], o);
        xp = *reinterpret_cast<const float4*>(pb + 3 * DD);
        o.x = fmaf(xp.x, c3, dl.x); o.y = fmaf(xp.y, c3, dl.y);
        o.z = fmaf(xp.z, c3, dl.z); o.w = fmaf(xp.w, c3, dl.w);
        __stcs(&o4[op + 3 * (DD / 4)], o);
    }
}

extern "C" void kernel_launch(void* const* d_in, const int* in_sizes, int n_in,
                              void* d_out, int out_size)
{
    const float* x0 = (const float*)d_in[0];   // inputs [B, D] f32
    const float* w  = (const float*)d_in[1];   // w [L, D, 1]  f32
    const float* b  = (const float*)d_in[2];   // b [L, D]     f32
    float* out      = (float*)d_out;           // [B, D]       f32

    const int B = in_sizes[0] / DD;
    const int smem_bytes = NST * 4 * DD * (int)sizeof(float);   // 196608

    static int sm_count = 0;
    if (sm_count == 0) {
        cudaDeviceGetAttribute(&sm_count, cudaDevAttrMultiProcessorCount, 0);
        if (sm_count <= 0) sm_count = 148;
        cudaFuncSetAttribute(crossnet_dcn_kernel,
                             cudaFuncAttributeMaxDynamicSharedMemorySize,
                             smem_bytes);
    }

    crossnet_dcn_kernel<<<sm_count, BLOCK, smem_bytes>>>(x0, w, b, out, B);
}